// round 15
// baseline (speedup 1.0000x reference)
#include <cuda_runtime.h>
#include <cuda_fp16.h>
#include <cstdint>

// Problem constants
#define BATCH   2
#define LSEQ    2048
#define DMODEL  1024
#define NHEADS  16
#define DK      64
#define MROWS   (BATCH * LSEQ)          // 4096
#define MSHIFT  1.0f                    // softmax shift (fp16-range-safe; cancels in 1/l)
#define NBH     (BATCH * NHEADS)        // 32
#define KCAP    2304                    // gathered capacity per bh (2 aligned groups)
#define WSCALE  256.0f                  // W pre-scale (pow2, exact)
#define WINV    (1.0f / 256.0f)

// Scratch
__device__ float  g_q  [NBH * LSEQ * DK];
__device__ float  g_k  [NBH * LSEQ * DK];
__device__ float  g_v  [NBH * LSEQ * DK];
__device__ __half g_kh [NBH * KCAP * DK];
__device__ __half g_kl [NBH * KCAP * DK];
__device__ __half g_vth[NBH * DK * KCAP];
__device__ __half g_vtl[NBH * DK * KCAP];
__device__ int    g_permq[NBH * KCAP];
__device__ int    g_permk[NBH * KCAP];
__device__ int    g_cnt[NBH * 2];
// pre-split GEMM operands (fp16 hi/lo)
__device__ __half g_ah[3 * MROWS * DMODEL];
__device__ __half g_al[3 * MROWS * DMODEL];
__device__ __half g_wh[3 * DMODEL * DMODEL];
__device__ __half g_wl[3 * DMODEL * DMODEL];

// ===========================================================================
// Helpers
// ===========================================================================
__device__ __forceinline__ uint32_t smem_to_u32(const void* p) {
    uint32_t a;
    asm("{ .reg .u64 t; cvta.to.shared.u64 t, %1; cvt.u32.u64 %0, t; }" : "=r"(a) : "l"(p));
    return a;
}
__device__ __forceinline__ void cp16(uint32_t dst, const void* src) {
    asm volatile("cp.async.cg.shared.global [%0], [%1], 16;" :: "r"(dst), "l"(src) : "memory");
}
#define CP_COMMIT asm volatile("cp.async.commit_group;" ::: "memory")
#define CP_WAIT1  asm volatile("cp.async.wait_group 1;" ::: "memory")
#define CP_WAIT0  asm volatile("cp.async.wait_group 0;" ::: "memory")

// split one float into fp16 hi/lo
__device__ __forceinline__ void splith(float x, __half& h, __half& l) {
    h = __float2half_rn(x);
    l = __float2half_rn(x - __half2float(h));
}
// pack two floats -> hi half2 (a in low), lo half2
__device__ __forceinline__ void split2h(float a, float b, uint32_t& h, uint32_t& l) {
    __half ha, la, hb, lb;
    splith(a, ha, la);
    splith(b, hb, lb);
    h = ((uint32_t)__half_as_ushort(hb) << 16) | __half_as_ushort(ha);
    l = ((uint32_t)__half_as_ushort(lb) << 16) | __half_as_ushort(la);
}

__device__ __forceinline__ void ldsm4(uint32_t& r0, uint32_t& r1, uint32_t& r2, uint32_t& r3,
                                      uint32_t addr) {
    asm volatile("ldmatrix.sync.aligned.m8n8.x4.shared.b16 {%0,%1,%2,%3}, [%4];"
                 : "=r"(r0), "=r"(r1), "=r"(r2), "=r"(r3) : "r"(addr));
}

// m16n8k16 fp16 mma, fp32 accumulate
__device__ __forceinline__ void mma_f16(float& d0, float& d1, float& d2, float& d3,
                                        uint32_t a0, uint32_t a1, uint32_t a2, uint32_t a3,
                                        uint32_t b0, uint32_t b1) {
    asm volatile("mma.sync.aligned.m16n8k16.row.col.f32.f16.f16.f32 "
                 "{%0,%1,%2,%3}, {%4,%5,%6,%7}, {%8,%9}, {%0,%1,%2,%3};"
                 : "+f"(d0), "+f"(d1), "+f"(d2), "+f"(d3)
                 : "r"(a0), "r"(a1), "r"(a2), "r"(a3), "r"(b0), "r"(b1));
}

// ===========================================================================
// Fused elementwise fp16 split for all 6 operands (job = blockIdx.y)
// jobs 0-2: query/key/value (scale 1); jobs 3-5: Wq/Wk/Wv (scale 256)
// ===========================================================================
__global__ void __launch_bounds__(256)
split_all(const float* __restrict__ q, const float* __restrict__ k,
          const float* __restrict__ v, const float* __restrict__ wq,
          const float* __restrict__ wk, const float* __restrict__ wv)
{
    const int job = blockIdx.y;
    const float* src;
    __half* h;
    __half* l;
    float scale;
    size_t n;
    if (job < 3) {
        src = (job == 0) ? q : (job == 1) ? k : v;
        h = g_ah + (size_t)job * MROWS * DMODEL;
        l = g_al + (size_t)job * MROWS * DMODEL;
        scale = 1.0f;
        n = (size_t)MROWS * DMODEL;
    } else {
        const int jz = job - 3;
        src = (jz == 0) ? wq : (jz == 1) ? wk : wv;
        h = g_wh + (size_t)jz * DMODEL * DMODEL;
        l = g_wl + (size_t)jz * DMODEL * DMODEL;
        scale = WSCALE;
        n = (size_t)DMODEL * DMODEL;
    }
    const size_t i = ((size_t)blockIdx.x * 256 + threadIdx.x) * 4;
    if (i >= n) return;
    float4 val = *(const float4*)(src + i);
    uint32_t h0, l0, h1, l1;
    split2h(val.x * scale, val.y * scale, h0, l0);
    split2h(val.z * scale, val.w * scale, h1, l1);
    *(uint2*)(h + i) = make_uint2(h0, h1);
    *(uint2*)(l + i) = make_uint2(l0, l1);
}

// ===========================================================================
// Projection GEMM: 3xFP16 (m16n8k16), 128(m) x 64(n) tiles for wave packing.
// Grid (32, 16, 3) = 1536 CTAs, 2 CTAs/SM.  C = (A (256W)^T)/256 + b.
// ===========================================================================
#define PSTRB  80
#define ATILEB (128 * PSTRB)             // 10240
#define WTILEB (64 * PSTRB)              // 5120
#define PSTAGE (2 * ATILEB + 2 * WTILEB) // 30720: AH, AL, WH, WL
#define PROJ_SMEM (2 * PSTAGE)           // 61440

__global__ void __launch_bounds__(256, 2)
proj_mma(const float* __restrict__ bq, const float* __restrict__ bk,
         const float* __restrict__ bv)
{
    extern __shared__ char smem[];
    const uint32_t sb = smem_to_u32(smem);
    const int tid  = threadIdx.x;
    const int w    = tid >> 5;
    const int lane = tid & 31;
    const int g    = lane >> 2;
    const int tg   = lane & 3;
    const int bm   = blockIdx.x * 128;
    const int bn   = blockIdx.y * 64;
    const int z    = blockIdx.z;

    const __half* AHg = g_ah + (size_t)z * MROWS * DMODEL;
    const __half* ALg = g_al + (size_t)z * MROWS * DMODEL;
    const __half* WHg = g_wh + (size_t)z * DMODEL * DMODEL;
    const __half* WLg = g_wl + (size_t)z * DMODEL * DMODEL;
    const float* bias = (z == 0) ? bq : (z == 1) ? bk : bv;
    float* out = (z == 0) ? g_q : (z == 1) ? g_k : g_v;

    // cp slots: A 512 segs (2/thread), W 256 segs (1/thread)
    int arow[2], ac8[2];
#pragma unroll
    for (int i = 0; i < 2; i++) {
        const int idx = i * 256 + tid;
        arow[i] = idx >> 2;
        ac8[i]  = (idx & 3) << 3;
    }
    const int wrow = tid >> 2;           // 0..63
    const int wc8  = (tid & 3) << 3;

    // prologue: chunks 0,1 (k-chunk = 32)
#pragma unroll
    for (int c = 0; c < 2; c++) {
        const int k0 = c * 32;
        const uint32_t st = sb + (uint32_t)c * PSTAGE;
#pragma unroll
        for (int i = 0; i < 2; i++) {
            const uint32_t off = arow[i] * PSTRB + ac8[i] * 2;
            const size_t ga = (size_t)(bm + arow[i]) * DMODEL + k0 + ac8[i];
            cp16(st + off,          AHg + ga);
            cp16(st + ATILEB + off, ALg + ga);
        }
        {
            const uint32_t off = wrow * PSTRB + wc8 * 2;
            const size_t gw = (size_t)(bn + wrow) * DMODEL + k0 + wc8;
            cp16(st + 2 * ATILEB + off,          WHg + gw);
            cp16(st + 2 * ATILEB + WTILEB + off, WLg + gw);
        }
        CP_COMMIT;
    }

    float o[8][4];
#pragma unroll
    for (int j = 0; j < 8; j++)
#pragma unroll
        for (int r = 0; r < 4; r++) o[j][r] = 0.f;

    const uint32_t aRowOff = (uint32_t)(16 * w + (lane & 15)) * PSTRB
                           + (uint32_t)(lane >> 4) * 16;
    const uint32_t wRowOff = (uint32_t)(lane & 7) * PSTRB + (uint32_t)(lane >> 3) * 16;

    for (int c = 0; c < 32; c++) {
        const int p = c & 1;
        if (c < 31) { CP_WAIT1; } else { CP_WAIT0; }
        __syncthreads();

        const uint32_t AHa = sb + (uint32_t)p * PSTAGE + aRowOff;
        const uint32_t ALa = AHa + ATILEB;
        const uint32_t WHb = sb + (uint32_t)p * PSTAGE + 2 * ATILEB + wRowOff;
        const uint32_t WLb = WHb + WTILEB;

        uint32_t ah[2][4], al[2][4];
        ldsm4(ah[0][0], ah[0][1], ah[0][2], ah[0][3], AHa);
        ldsm4(ah[1][0], ah[1][1], ah[1][2], ah[1][3], AHa + 32);
        ldsm4(al[0][0], al[0][1], al[0][2], al[0][3], ALa);
        ldsm4(al[1][0], al[1][1], al[1][2], al[1][3], ALa + 32);

#pragma unroll
        for (int j = 0; j < 8; j++) {
            uint32_t wh[4], wl[4];
            ldsm4(wh[0], wh[1], wh[2], wh[3], WHb + (uint32_t)j * 8 * PSTRB);
            ldsm4(wl[0], wl[1], wl[2], wl[3], WLb + (uint32_t)j * 8 * PSTRB);
#pragma unroll
            for (int s = 0; s < 2; s++) {
                mma_f16(o[j][0], o[j][1], o[j][2], o[j][3],
                        ah[s][0], ah[s][1], ah[s][2], ah[s][3], wh[2 * s], wh[2 * s + 1]);
                mma_f16(o[j][0], o[j][1], o[j][2], o[j][3],
                        al[s][0], al[s][1], al[s][2], al[s][3], wh[2 * s], wh[2 * s + 1]);
                mma_f16(o[j][0], o[j][1], o[j][2], o[j][3],
                        ah[s][0], ah[s][1], ah[s][2], ah[s][3], wl[2 * s], wl[2 * s + 1]);
            }
        }
        __syncthreads();
        if (c + 2 < 32) {
            const int k0 = (c + 2) * 32;
            const uint32_t st = sb + (uint32_t)p * PSTAGE;
#pragma unroll
            for (int i = 0; i < 2; i++) {
                const uint32_t off = arow[i] * PSTRB + ac8[i] * 2;
                const size_t ga = (size_t)(bm + arow[i]) * DMODEL + k0 + ac8[i];
                cp16(st + off,          AHg + ga);
                cp16(st + ATILEB + off, ALg + ga);
            }
            {
                const uint32_t off = wrow * PSTRB + wc8 * 2;
                const size_t gw = (size_t)(bn + wrow) * DMODEL + k0 + wc8;
                cp16(st + 2 * ATILEB + off,          WHg + gw);
                cp16(st + 2 * ATILEB + WTILEB + off, WLg + gw);
            }
            CP_COMMIT;
        }
    }

    // epilogue: undo W scale, add bias, head-split write (bn is 64-aligned -> one head)
    const int m0 = bm + 16 * w + g;
    const int m1 = m0 + 8;
    const int b0i = m0 >> 11, l0i = m0 & 2047;
    const int b1i = m1 >> 11, l1i = m1 & 2047;
    const int hh = bn >> 6;
#pragma unroll
    for (int j = 0; j < 8; j++) {
        const int n0 = bn + 8 * j + 2 * tg;
        const float2 bv2 = *(const float2*)(bias + n0);
        const int d = n0 & 63;
        float* o0 = out + (((size_t)(b0i * NHEADS + hh) * LSEQ) + l0i) * DK + d;
        float* o1 = out + (((size_t)(b1i * NHEADS + hh) * LSEQ) + l1i) * DK + d;
        *(float2*)o0 = make_float2(fmaf(o[j][0], WINV, bv2.x), fmaf(o[j][1], WINV, bv2.y));
        *(float2*)o1 = make_float2(fmaf(o[j][2], WINV, bv2.x), fmaf(o[j][3], WINV, bv2.y));
    }
}

// ===========================================================================
// LSH partition prep (unchanged)
// ===========================================================================
__global__ void __launch_bounds__(64) build_perm(const int* __restrict__ hq,
                                                 const int* __restrict__ hk)
{
    const int bh   = blockIdx.x;
    const int wid  = threadIdx.x >> 5;
    const int lane = threadIdx.x & 31;
    const int* hsh = (wid ? hq : hk) + bh * LSEQ;
    int* pm = (wid ? g_permq : g_permk) + bh * KCAP;
    const int align = wid ? 128 : 64;

    int c0 = 0;
    for (int i = 0; i < LSEQ / 32; i++) {
        const int v = hsh[i * 32 + lane];
        c0 += __popc(__ballot_sync(0xffffffffu, v == 0));
    }
    const int b1 = (c0 + align - 1) & ~(align - 1);
    int o0 = 0, o1 = b1;
    for (int i = 0; i < LSEQ / 32; i++) {
        const int v = hsh[i * 32 + lane];
        const unsigned m  = __ballot_sync(0xffffffffu, v == 0);
        const unsigned lt = (1u << lane) - 1u;
        const int pos = (v == 0) ? o0 + __popc(m & lt) : o1 + __popc(~m & lt);
        pm[pos] = i * 32 + lane;
        o0 += __popc(m);
        o1 += 32 - __popc(m);
    }
    for (int i = c0 + lane; i < b1; i += 32) pm[i] = -1;
    for (int i = o1 + lane; i < KCAP; i += 32) pm[i] = -1;
    if (lane == 0) g_cnt[bh * 2 + (wid ? 0 : 1)] = c0;
}

// ===========================================================================
// Gather + split K (fp16); gather + transpose + split V (fp16)  (unchanged)
// ===========================================================================
__global__ void __launch_bounds__(256) gather_split_k()
{
    const int bh  = blockIdx.z;
    const int idx = blockIdx.x * 256 + threadIdx.x;
    const int row = idx >> 4;
    const int c4  = (idx & 15) << 2;
    const int src = g_permk[bh * KCAP + row];
    float4 v = make_float4(0.f, 0.f, 0.f, 0.f);
    if (src >= 0) v = *(const float4*)(g_k + ((size_t)(bh * LSEQ + src)) * DK + c4);
    uint32_t h0, l0, h1, l1;
    split2h(v.x, v.y, h0, l0);
    split2h(v.z, v.w, h1, l1);
    const size_t o = ((size_t)(bh * KCAP + row)) * DK + c4;
    *(uint2*)(g_kh + o) = make_uint2(h0, h1);
    *(uint2*)(g_kl + o) = make_uint2(l0, l1);
}

__global__ void __launch_bounds__(256) gather_transpose_v()
{
    __shared__ float tile[32][33];
    const int lb = blockIdx.x * 32;
    const int db = blockIdx.y * 32;
    const int bh = blockIdx.z;
    const int r = threadIdx.x >> 3;
    const int c = (threadIdx.x & 7) << 2;
    const int src = g_permk[bh * KCAP + lb + r];
    float4 v = make_float4(0.f, 0.f, 0.f, 0.f);
    if (src >= 0) v = *(const float4*)(g_v + ((size_t)(bh * LSEQ + src)) * DK + db + c);
    tile[r][c] = v.x; tile[r][c + 1] = v.y; tile[r][c + 2] = v.z; tile[r][c + 3] = v.w;
    __syncthreads();
    uint32_t h0, l0, h1, l1;
    split2h(tile[c][r], tile[c + 1][r], h0, l0);
    split2h(tile[c + 2][r], tile[c + 3][r], h1, l1);
    const size_t o = ((size_t)bh * DK + db + r) * KCAP + lb + c;
    *(uint2*)(g_vth + o) = make_uint2(h0, h1);
    *(uint2*)(g_vtl + o) = make_uint2(l0, l1);
}

// ===========================================================================
// Partitioned 3xFP16 flash attention (m16n8k16), P = exp(0.125 s - 1).
// (unchanged from R14)
// ===========================================================================
#define STRAB 144
#define ATILE (64 * STRAB)               // 9216
#define ASTAGE (4 * ATILE)               // 36864
#define ATT_SMEM (2 * ASTAGE)            // 73728

__device__ __forceinline__ void load_kv(uint32_t sb, int p, int t,
                                        const __half* __restrict__ khg,
                                        const __half* __restrict__ klg,
                                        const __half* __restrict__ vthg,
                                        const __half* __restrict__ vtlg,
                                        const int* rowp, const int* c8p)
{
    const int kv0 = t * 64;
    const uint32_t so = sb + (uint32_t)p * ASTAGE;
#pragma unroll
    for (int i = 0; i < 2; i++) {
        const uint32_t off = rowp[i] * STRAB + c8p[i] * 2;
        cp16(so + off,             khg  + (size_t)(kv0 + rowp[i]) * DK + c8p[i]);
        cp16(so + ATILE + off,     klg  + (size_t)(kv0 + rowp[i]) * DK + c8p[i]);
        cp16(so + 2 * ATILE + off, vthg + (size_t)rowp[i] * KCAP + kv0 + c8p[i]);
        cp16(so + 3 * ATILE + off, vtlg + (size_t)rowp[i] * KCAP + kv0 + c8p[i]);
    }
}

__global__ void __launch_bounds__(256, 1)
attn_mma(const float* __restrict__ Q, float* __restrict__ out)
{
    extern __shared__ char smem[];
    const uint32_t sb = smem_to_u32(smem);
    const int tid  = threadIdx.x;
    const int w    = tid >> 5;
    const int lane = tid & 31;
    const int g    = lane >> 2;
    const int tg   = lane & 3;
    const int h = blockIdx.y, b = blockIdx.z;
    const int bh = b * NHEADS + h;

    const int cq0 = g_cnt[bh * 2];
    const int ck0 = g_cnt[bh * 2 + 1];
    int xt = blockIdx.x;
    const int qt0 = (cq0 + 127) >> 7;
    int q0, ckg, kvb;
    if (xt < qt0) {
        q0 = xt * 128; ckg = ck0; kvb = 0;
    } else {
        xt -= qt0;
        const int cq1 = LSEQ - cq0;
        if (xt >= ((cq1 + 127) >> 7)) return;
        q0  = ((cq0 + 127) & ~127) + xt * 128;
        ckg = LSEQ - ck0;
        kvb = (ck0 + 63) & ~63;
    }
    const int nkt = (ckg + 63) >> 6;

    const __half* khg  = g_kh  + ((size_t)bh * KCAP + kvb) * DK;
    const __half* klg  = g_kl  + ((size_t)bh * KCAP + kvb) * DK;
    const __half* vthg = g_vth + (size_t)bh * DK * KCAP + kvb;
    const __half* vtlg = g_vtl + (size_t)bh * DK * KCAP + kvb;
    const int*    pq   = g_permq + bh * KCAP;

    int rowp[2], c8p[2];
#pragma unroll
    for (int i = 0; i < 2; i++) {
        const int idx = i * 256 + tid;
        rowp[i] = idx >> 3;
        c8p[i]  = (idx & 7) << 3;
    }

    const int src0 = pq[q0 + 16 * w + g];
    const int src1 = pq[q0 + 16 * w + g + 8];
    uint32_t qh[4][4], ql[4][4];
    {
        const float* qg0 = Q + ((size_t)bh * LSEQ + max(src0, 0)) * DK;
        const float* qg1 = Q + ((size_t)bh * LSEQ + max(src1, 0)) * DK;
#pragma unroll
        for (int s = 0; s < 4; s++) {
            const int k0 = 16 * s + 2 * tg;
            split2h(qg0[k0],     qg0[k0 + 1], qh[s][0], ql[s][0]);
            split2h(qg1[k0],     qg1[k0 + 1], qh[s][1], ql[s][1]);
            split2h(qg0[k0 + 8], qg0[k0 + 9], qh[s][2], ql[s][2]);
            split2h(qg1[k0 + 8], qg1[k0 + 9], qh[s][3], ql[s][3]);
        }
    }

    load_kv(sb, 0, 0, khg, klg, vthg, vtlg, rowp, c8p);
    CP_COMMIT;
    load_kv(sb, 1, 1, khg, klg, vthg, vtlg, rowp, c8p);
    CP_COMMIT;

    float o[8][4];
#pragma unroll
    for (int n = 0; n < 8; n++)
#pragma unroll
        for (int r = 0; r < 4; r++) o[n][r] = 0.f;
    float l0 = 0.f, l1 = 0.f;

    const uint32_t kRowOff = (uint32_t)(lane & 7) * STRAB + (uint32_t)(lane >> 3) * 16;
    const uint32_t vRowOff = (uint32_t)((lane & 7) + ((lane >> 4) << 3)) * STRAB
                           + (uint32_t)((lane >> 3) & 1) * 16;

    for (int t = 0; t < nkt; t++) {
        const int p = t & 1;
        if (t < nkt - 1) { CP_WAIT1; } else { CP_WAIT0; }
        __syncthreads();

        const uint32_t stb = sb + (uint32_t)p * ASTAGE;
        const uint32_t kHa = stb + kRowOff;
        const uint32_t kLa = kHa + ATILE;
        const uint32_t vHa = stb + 2 * ATILE + vRowOff;
        const uint32_t vLa = vHa + ATILE;

#pragma unroll
        for (int jj = 0; jj < 4; jj++) {
            float cA[2][4], cB[2][4];
#pragma unroll
            for (int u = 0; u < 2; u++)
#pragma unroll
                for (int r = 0; r < 4; r++) { cA[u][r] = 0.f; cB[u][r] = 0.f; }
#pragma unroll
            for (int u = 0; u < 2; u++) {
                const uint32_t kjh = kHa + (uint32_t)(2 * jj + u) * 8 * STRAB;
                const uint32_t kjl = kLa + (uint32_t)(2 * jj + u) * 8 * STRAB;
                uint32_t kf[8], lf[8];
                ldsm4(kf[0], kf[1], kf[2], kf[3], kjh);
                ldsm4(kf[4], kf[5], kf[6], kf[7], kjh + 64);
                ldsm4(lf[0], lf[1], lf[2], lf[3], kjl);
                ldsm4(lf[4], lf[5], lf[6], lf[7], kjl + 64);
#pragma unroll
                for (int s = 0; s < 4; s++) {
                    mma_f16(cA[u][0], cA[u][1], cA[u][2], cA[u][3],
                            qh[s][0], qh[s][1], qh[s][2], qh[s][3], kf[2 * s], kf[2 * s + 1]);
                    mma_f16(cB[u][0], cB[u][1], cB[u][2], cB[u][3],
                            ql[s][0], ql[s][1], ql[s][2], ql[s][3], kf[2 * s], kf[2 * s + 1]);
                    mma_f16(cB[u][0], cB[u][1], cB[u][2], cB[u][3],
                            qh[s][0], qh[s][1], qh[s][2], qh[s][3], lf[2 * s], lf[2 * s + 1]);
                }
            }
            uint32_t pA[4], pL[4];
#pragma unroll
            for (int u = 0; u < 2; u++) {
                const int idx0 = t * 64 + jj * 16 + u * 8 + 2 * tg;
                const bool v0 = idx0 < ckg;
                const bool v1 = idx0 + 1 < ckg;
                const float p0 = v0 ? __expf(fmaf(cA[u][0] + cB[u][0], 0.125f, -MSHIFT)) : 0.f;
                const float p1 = v1 ? __expf(fmaf(cA[u][1] + cB[u][1], 0.125f, -MSHIFT)) : 0.f;
                const float p2 = v0 ? __expf(fmaf(cA[u][2] + cB[u][2], 0.125f, -MSHIFT)) : 0.f;
                const float p3 = v1 ? __expf(fmaf(cA[u][3] + cB[u][3], 0.125f, -MSHIFT)) : 0.f;
                l0 += p0 + p1;
                l1 += p2 + p3;
                split2h(p0, p1, pA[0 + u * 2], pL[0 + u * 2]);
                split2h(p2, p3, pA[1 + u * 2], pL[1 + u * 2]);
            }
            uint32_t vf[16], wf[16];
            const uint32_t vj = vHa + (uint32_t)jj * 32;
            const uint32_t wj = vLa + (uint32_t)jj * 32;
#pragma unroll
            for (int pr = 0; pr < 4; pr++) {
                ldsm4(vf[4 * pr], vf[4 * pr + 1], vf[4 * pr + 2], vf[4 * pr + 3],
                      vj + (uint32_t)pr * 16 * STRAB);
                ldsm4(wf[4 * pr], wf[4 * pr + 1], wf[4 * pr + 2], wf[4 * pr + 3],
                      wj + (uint32_t)pr * 16 * STRAB);
            }
#pragma unroll
            for (int n = 0; n < 8; n++) {
                const int bi = 2 * n;
                mma_f16(o[n][0], o[n][1], o[n][2], o[n][3],
                        pA[0], pA[1], pA[2], pA[3], vf[bi], vf[bi + 1]);
            }
#pragma unroll
            for (int n = 0; n < 8; n++) {
                const int bi = 2 * n;
                mma_f16(o[n][0], o[n][1], o[n][2], o[n][3],
                        pL[0], pL[1], pL[2], pL[3], vf[bi], vf[bi + 1]);
            }
#pragma unroll
            for (int n = 0; n < 8; n++) {
                const int bi = 2 * n;
                mma_f16(o[n][0], o[n][1], o[n][2], o[n][3],
                        pA[0], pA[1], pA[2], pA[3], wf[bi], wf[bi + 1]);
            }
        }
        __syncthreads();
        if (t + 2 < nkt) {
            load_kv(sb, p, t + 2, khg, klg, vthg, vtlg, rowp, c8p);
            CP_COMMIT;
        }
    }

    l0 += __shfl_xor_sync(0xffffffffu, l0, 1);
    l0 += __shfl_xor_sync(0xffffffffu, l0, 2);
    l1 += __shfl_xor_sync(0xffffffffu, l1, 1);
    l1 += __shfl_xor_sync(0xffffffffu, l1, 2);
    const float il0 = 1.f / l0;
    const float il1 = 1.f / l1;

    if (src0 >= 0) {
        float* orow0 = out + (size_t)(b * LSEQ + src0) * DMODEL + h * DK + 2 * tg;
#pragma unroll
        for (int n = 0; n < 8; n++)
            *(float2*)(orow0 + 8 * n) = make_float2(o[n][0] * il0, o[n][1] * il0);
    }
    if (src1 >= 0) {
        float* orow1 = out + (size_t)(b * LSEQ + src1) * DMODEL + h * DK + 2 * tg;
#pragma unroll
        for (int n = 0; n < 8; n++)
            *(float2*)(orow1 + 8 * n) = make_float2(o[n][2] * il1, o[n][3] * il1);
    }
}

// ===========================================================================
// Launch
// ===========================================================================
extern "C" void kernel_launch(void* const* d_in, const int* in_sizes, int n_in,
                              void* d_out, int out_size)
{
    const float* query  = (const float*)d_in[0];
    const float* key    = (const float*)d_in[1];
    const float* value  = (const float*)d_in[2];
    const int*   hash_q = (const int*)d_in[3];
    const int*   hash_k = (const int*)d_in[4];
    const float* Wq     = (const float*)d_in[5];
    const float* bq     = (const float*)d_in[6];
    const float* Wk     = (const float*)d_in[7];
    const float* bk     = (const float*)d_in[8];
    const float* Wv     = (const float*)d_in[9];
    const float* bv     = (const float*)d_in[10];
    float* out = (float*)d_out;

    float* gq;
    cudaGetSymbolAddress((void**)&gq, g_q);

    cudaFuncSetAttribute(proj_mma, cudaFuncAttributeMaxDynamicSharedMemorySize, PROJ_SMEM);
    cudaFuncSetAttribute(attn_mma, cudaFuncAttributeMaxDynamicSharedMemorySize, ATT_SMEM);

    // fused pre-split of all 6 operands
    dim3 sg(MROWS * DMODEL / (4 * 256), 6);  // (4096, 6); W jobs early-exit above 1024
    split_all<<<sg, 256>>>(query, key, value, Wq, Wk, Wv);

    dim3 pg(MROWS / 128, DMODEL / 64, 3);    // (32, 16, 3) = 1536 CTAs
    proj_mma<<<pg, 256, PROJ_SMEM>>>(bq, bk, bv);

    build_perm<<<NBH, 64>>>(hash_q, hash_k);

    dim3 gk(KCAP * (DK / 4) / 256, 1, NBH);  // (144, 1, 32)
    gather_split_k<<<gk, 256>>>();
    dim3 tv(KCAP / 32, DK / 32, NBH);        // (72, 2, 32)
    gather_transpose_v<<<tv, 256>>>();

    dim3 ag(17, NHEADS, BATCH);
    attn_mma<<<ag, 256, ATT_SMEM>>>(gq, out);
}

// round 16
// speedup vs baseline: 1.0452x; 1.0452x over previous
#include <cuda_runtime.h>
#include <cuda_fp16.h>
#include <cstdint>

// Problem constants
#define BATCH   2
#define LSEQ    2048
#define DMODEL  1024
#define NHEADS  16
#define DK      64
#define MROWS   (BATCH * LSEQ)          // 4096
#define MSHIFT  1.0f                    // softmax shift (fp16-range-safe; cancels in 1/l)
#define NBH     (BATCH * NHEADS)        // 32
#define KCAP    2304                    // gathered capacity per bh (2 aligned groups)
#define WSCALE  256.0f                  // W pre-scale (pow2, exact)
#define WINV    (1.0f / 256.0f)

// Scratch
__device__ float  g_q  [NBH * LSEQ * DK];
__device__ float  g_k  [NBH * LSEQ * DK];
__device__ float  g_v  [NBH * LSEQ * DK];
__device__ __half g_kh [NBH * KCAP * DK];
__device__ __half g_kl [NBH * KCAP * DK];
__device__ __half g_vth[NBH * DK * KCAP];
__device__ __half g_vtl[NBH * DK * KCAP];
__device__ int    g_permq[NBH * KCAP];
__device__ int    g_permk[NBH * KCAP];
__device__ int    g_cnt[NBH * 2];
// pre-split GEMM operands (fp16 hi/lo)
__device__ __half g_ah[3 * MROWS * DMODEL];
__device__ __half g_al[3 * MROWS * DMODEL];
__device__ __half g_wh[3 * DMODEL * DMODEL];
__device__ __half g_wl[3 * DMODEL * DMODEL];

// ===========================================================================
// Helpers
// ===========================================================================
__device__ __forceinline__ uint32_t smem_to_u32(const void* p) {
    uint32_t a;
    asm("{ .reg .u64 t; cvta.to.shared.u64 t, %1; cvt.u32.u64 %0, t; }" : "=r"(a) : "l"(p));
    return a;
}
__device__ __forceinline__ void cp16(uint32_t dst, const void* src) {
    asm volatile("cp.async.cg.shared.global [%0], [%1], 16;" :: "r"(dst), "l"(src) : "memory");
}
#define CP_COMMIT asm volatile("cp.async.commit_group;" ::: "memory")
#define CP_WAIT1  asm volatile("cp.async.wait_group 1;" ::: "memory")
#define CP_WAIT0  asm volatile("cp.async.wait_group 0;" ::: "memory")

// split one float into fp16 hi/lo
__device__ __forceinline__ void splith(float x, __half& h, __half& l) {
    h = __float2half_rn(x);
    l = __float2half_rn(x - __half2float(h));
}
// pack two floats -> hi half2 (a in low), lo half2
__device__ __forceinline__ void split2h(float a, float b, uint32_t& h, uint32_t& l) {
    __half ha, la, hb, lb;
    splith(a, ha, la);
    splith(b, hb, lb);
    h = ((uint32_t)__half_as_ushort(hb) << 16) | __half_as_ushort(ha);
    l = ((uint32_t)__half_as_ushort(lb) << 16) | __half_as_ushort(la);
}

__device__ __forceinline__ void ldsm4(uint32_t& r0, uint32_t& r1, uint32_t& r2, uint32_t& r3,
                                      uint32_t addr) {
    asm volatile("ldmatrix.sync.aligned.m8n8.x4.shared.b16 {%0,%1,%2,%3}, [%4];"
                 : "=r"(r0), "=r"(r1), "=r"(r2), "=r"(r3) : "r"(addr));
}

// m16n8k16 fp16 mma, fp32 accumulate
__device__ __forceinline__ void mma_f16(float& d0, float& d1, float& d2, float& d3,
                                        uint32_t a0, uint32_t a1, uint32_t a2, uint32_t a3,
                                        uint32_t b0, uint32_t b1) {
    asm volatile("mma.sync.aligned.m16n8k16.row.col.f32.f16.f16.f32 "
                 "{%0,%1,%2,%3}, {%4,%5,%6,%7}, {%8,%9}, {%0,%1,%2,%3};"
                 : "+f"(d0), "+f"(d1), "+f"(d2), "+f"(d3)
                 : "r"(a0), "r"(a1), "r"(a2), "r"(a3), "r"(b0), "r"(b1));
}

// ===========================================================================
// Fused elementwise fp16 split for all 6 operands (job = blockIdx.y)
// ===========================================================================
__global__ void __launch_bounds__(256)
split_all(const float* __restrict__ q, const float* __restrict__ k,
          const float* __restrict__ v, const float* __restrict__ wq,
          const float* __restrict__ wk, const float* __restrict__ wv)
{
    const int job = blockIdx.y;
    const float* src;
    __half* h;
    __half* l;
    float scale;
    size_t n;
    if (job < 3) {
        src = (job == 0) ? q : (job == 1) ? k : v;
        h = g_ah + (size_t)job * MROWS * DMODEL;
        l = g_al + (size_t)job * MROWS * DMODEL;
        scale = 1.0f;
        n = (size_t)MROWS * DMODEL;
    } else {
        const int jz = job - 3;
        src = (jz == 0) ? wq : (jz == 1) ? wk : wv;
        h = g_wh + (size_t)jz * DMODEL * DMODEL;
        l = g_wl + (size_t)jz * DMODEL * DMODEL;
        scale = WSCALE;
        n = (size_t)DMODEL * DMODEL;
    }
    const size_t i = ((size_t)blockIdx.x * 256 + threadIdx.x) * 4;
    if (i >= n) return;
    float4 val = *(const float4*)(src + i);
    uint32_t h0, l0, h1, l1;
    split2h(val.x * scale, val.y * scale, h0, l0);
    split2h(val.z * scale, val.w * scale, h1, l1);
    *(uint2*)(h + i) = make_uint2(h0, h1);
    *(uint2*)(l + i) = make_uint2(l0, l1);
}

// ===========================================================================
// Projection GEMM (R14-proven): 3xFP16 m16n8k16, 128x128 tiles, k-chunk 32,
// 2 CTAs/SM.  C = (A (256W)^T)/256 + b.
// ===========================================================================
#define PSTRB  80
#define PTILEB (128 * PSTRB)             // 10240
#define PSTAGE (4 * PTILEB)              // 40960
#define PROJ_SMEM (2 * PSTAGE)           // 81920

__global__ void __launch_bounds__(256, 2)
proj_mma(const float* __restrict__ bq, const float* __restrict__ bk,
         const float* __restrict__ bv)
{
    extern __shared__ char smem[];
    const uint32_t sb = smem_to_u32(smem);
    const int tid  = threadIdx.x;
    const int w    = tid >> 5;
    const int lane = tid & 31;
    const int g    = lane >> 2;
    const int tg   = lane & 3;
    const int bm   = blockIdx.x * 128;
    const int bn   = blockIdx.y * 128;
    const int z    = blockIdx.z;

    const __half* AHg = g_ah + (size_t)z * MROWS * DMODEL;
    const __half* ALg = g_al + (size_t)z * MROWS * DMODEL;
    const __half* WHg = g_wh + (size_t)z * DMODEL * DMODEL;
    const __half* WLg = g_wl + (size_t)z * DMODEL * DMODEL;
    const float* bias = (z == 0) ? bq : (z == 1) ? bk : bv;
    float* out = (z == 0) ? g_q : (z == 1) ? g_k : g_v;

    int rowp[2], c8p[2];
#pragma unroll
    for (int i = 0; i < 2; i++) {
        const int idx = i * 256 + tid;
        rowp[i] = idx >> 2;
        c8p[i]  = (idx & 3) << 3;
    }

#pragma unroll
    for (int c = 0; c < 2; c++) {
        const int k0 = c * 32;
#pragma unroll
        for (int i = 0; i < 2; i++) {
            const uint32_t so = (uint32_t)c * PSTAGE + rowp[i] * PSTRB + c8p[i] * 2;
            const size_t ga = (size_t)(bm + rowp[i]) * DMODEL + k0 + c8p[i];
            const size_t gw = (size_t)(bn + rowp[i]) * DMODEL + k0 + c8p[i];
            cp16(sb + so,              AHg + ga);
            cp16(sb + so + PTILEB,     ALg + ga);
            cp16(sb + so + 2 * PTILEB, WHg + gw);
            cp16(sb + so + 3 * PTILEB, WLg + gw);
        }
        CP_COMMIT;
    }

    float o[16][4];
#pragma unroll
    for (int j = 0; j < 16; j++)
#pragma unroll
        for (int r = 0; r < 4; r++) o[j][r] = 0.f;

    const uint32_t aRowOff = (uint32_t)(16 * w + (lane & 15)) * PSTRB
                           + (uint32_t)(lane >> 4) * 16;
    const uint32_t wRowOff = (uint32_t)(lane & 7) * PSTRB + (uint32_t)(lane >> 3) * 16;

    for (int c = 0; c < 32; c++) {
        const int p = c & 1;
        if (c < 31) { CP_WAIT1; } else { CP_WAIT0; }
        __syncthreads();

        const uint32_t AHa = sb + (uint32_t)p * PSTAGE + aRowOff;
        const uint32_t ALa = AHa + PTILEB;
        const uint32_t WHb = sb + (uint32_t)p * PSTAGE + 2 * PTILEB + wRowOff;
        const uint32_t WLb = WHb + PTILEB;

        uint32_t ah[2][4], al[2][4];
        ldsm4(ah[0][0], ah[0][1], ah[0][2], ah[0][3], AHa);
        ldsm4(ah[1][0], ah[1][1], ah[1][2], ah[1][3], AHa + 32);
        ldsm4(al[0][0], al[0][1], al[0][2], al[0][3], ALa);
        ldsm4(al[1][0], al[1][1], al[1][2], al[1][3], ALa + 32);

#pragma unroll
        for (int j = 0; j < 16; j++) {
            uint32_t wh[4], wl[4];
            ldsm4(wh[0], wh[1], wh[2], wh[3], WHb + (uint32_t)j * 8 * PSTRB);
            ldsm4(wl[0], wl[1], wl[2], wl[3], WLb + (uint32_t)j * 8 * PSTRB);
#pragma unroll
            for (int s = 0; s < 2; s++) {
                mma_f16(o[j][0], o[j][1], o[j][2], o[j][3],
                        ah[s][0], ah[s][1], ah[s][2], ah[s][3], wh[2 * s], wh[2 * s + 1]);
                mma_f16(o[j][0], o[j][1], o[j][2], o[j][3],
                        al[s][0], al[s][1], al[s][2], al[s][3], wh[2 * s], wh[2 * s + 1]);
                mma_f16(o[j][0], o[j][1], o[j][2], o[j][3],
                        ah[s][0], ah[s][1], ah[s][2], ah[s][3], wl[2 * s], wl[2 * s + 1]);
            }
        }
        __syncthreads();
        if (c + 2 < 32) {
            const int k0 = (c + 2) * 32;
#pragma unroll
            for (int i = 0; i < 2; i++) {
                const uint32_t so = (uint32_t)p * PSTAGE + rowp[i] * PSTRB + c8p[i] * 2;
                const size_t ga = (size_t)(bm + rowp[i]) * DMODEL + k0 + c8p[i];
                const size_t gw = (size_t)(bn + rowp[i]) * DMODEL + k0 + c8p[i];
                cp16(sb + so,              AHg + ga);
                cp16(sb + so + PTILEB,     ALg + ga);
                cp16(sb + so + 2 * PTILEB, WHg + gw);
                cp16(sb + so + 3 * PTILEB, WLg + gw);
            }
            CP_COMMIT;
        }
    }

    const int m0 = bm + 16 * w + g;
    const int m1 = m0 + 8;
    const int b0i = m0 >> 11, l0i = m0 & 2047;
    const int b1i = m1 >> 11, l1i = m1 & 2047;
#pragma unroll
    for (int j = 0; j < 16; j++) {
        const int n0 = bn + 8 * j + 2 * tg;
        const float2 bv2 = *(const float2*)(bias + n0);
        const int h = n0 >> 6, d = n0 & 63;
        float* o0 = out + (((size_t)(b0i * NHEADS + h) * LSEQ) + l0i) * DK + d;
        float* o1 = out + (((size_t)(b1i * NHEADS + h) * LSEQ) + l1i) * DK + d;
        *(float2*)o0 = make_float2(fmaf(o[j][0], WINV, bv2.x), fmaf(o[j][1], WINV, bv2.y));
        *(float2*)o1 = make_float2(fmaf(o[j][2], WINV, bv2.x), fmaf(o[j][3], WINV, bv2.y));
    }
}

// ===========================================================================
// LSH partition prep (unchanged)
// ===========================================================================
__global__ void __launch_bounds__(64) build_perm(const int* __restrict__ hq,
                                                 const int* __restrict__ hk)
{
    const int bh   = blockIdx.x;
    const int wid  = threadIdx.x >> 5;
    const int lane = threadIdx.x & 31;
    const int* hsh = (wid ? hq : hk) + bh * LSEQ;
    int* pm = (wid ? g_permq : g_permk) + bh * KCAP;
    const int align = wid ? 128 : 64;

    int c0 = 0;
    for (int i = 0; i < LSEQ / 32; i++) {
        const int v = hsh[i * 32 + lane];
        c0 += __popc(__ballot_sync(0xffffffffu, v == 0));
    }
    const int b1 = (c0 + align - 1) & ~(align - 1);
    int o0 = 0, o1 = b1;
    for (int i = 0; i < LSEQ / 32; i++) {
        const int v = hsh[i * 32 + lane];
        const unsigned m  = __ballot_sync(0xffffffffu, v == 0);
        const unsigned lt = (1u << lane) - 1u;
        const int pos = (v == 0) ? o0 + __popc(m & lt) : o1 + __popc(~m & lt);
        pm[pos] = i * 32 + lane;
        o0 += __popc(m);
        o1 += 32 - __popc(m);
    }
    for (int i = c0 + lane; i < b1; i += 32) pm[i] = -1;
    for (int i = o1 + lane; i < KCAP; i += 32) pm[i] = -1;
    if (lane == 0) g_cnt[bh * 2 + (wid ? 0 : 1)] = c0;
}

// ===========================================================================
// Merged gather: y=0 -> K gather+split; y=1 -> V gather+transpose+split
// grid (144, 2, NBH)
// ===========================================================================
__global__ void __launch_bounds__(256) gather_kv()
{
    __shared__ float tile[32][33];
    const int bh = blockIdx.z;

    if (blockIdx.y == 0) {
        // K: 144 CTAs x 256 threads = KCAP*16 slots
        const int idx = blockIdx.x * 256 + threadIdx.x;
        const int row = idx >> 4;
        const int c4  = (idx & 15) << 2;
        const int src = g_permk[bh * KCAP + row];
        float4 v = make_float4(0.f, 0.f, 0.f, 0.f);
        if (src >= 0) v = *(const float4*)(g_k + ((size_t)(bh * LSEQ + src)) * DK + c4);
        uint32_t h0, l0, h1, l1;
        split2h(v.x, v.y, h0, l0);
        split2h(v.z, v.w, h1, l1);
        const size_t o = ((size_t)(bh * KCAP + row)) * DK + c4;
        *(uint2*)(g_kh + o) = make_uint2(h0, h1);
        *(uint2*)(g_kl + o) = make_uint2(l0, l1);
    } else {
        // V: 144 CTAs = 72 lb-tiles x 2 db-tiles
        const int lb = (blockIdx.x >> 1) * 32;
        const int db = (blockIdx.x & 1) * 32;
        const int r = threadIdx.x >> 3;
        const int c = (threadIdx.x & 7) << 2;
        const int src = g_permk[bh * KCAP + lb + r];
        float4 v = make_float4(0.f, 0.f, 0.f, 0.f);
        if (src >= 0) v = *(const float4*)(g_v + ((size_t)(bh * LSEQ + src)) * DK + db + c);
        tile[r][c] = v.x; tile[r][c + 1] = v.y; tile[r][c + 2] = v.z; tile[r][c + 3] = v.w;
        __syncthreads();
        uint32_t h0, l0, h1, l1;
        split2h(tile[c][r], tile[c + 1][r], h0, l0);
        split2h(tile[c + 2][r], tile[c + 3][r], h1, l1);
        const size_t o = ((size_t)bh * DK + db + r) * KCAP + lb + c;
        *(uint2*)(g_vth + o) = make_uint2(h0, h1);
        *(uint2*)(g_vtl + o) = make_uint2(l0, l1);
    }
}

// ===========================================================================
// Partitioned 3xFP16 flash attention (m16n8k16), P = exp(0.125 s - 1).
// (unchanged from R14)
// ===========================================================================
#define STRAB 144
#define ATILE (64 * STRAB)               // 9216
#define ASTAGE (4 * ATILE)               // 36864
#define ATT_SMEM (2 * ASTAGE)            // 73728

__device__ __forceinline__ void load_kv(uint32_t sb, int p, int t,
                                        const __half* __restrict__ khg,
                                        const __half* __restrict__ klg,
                                        const __half* __restrict__ vthg,
                                        const __half* __restrict__ vtlg,
                                        const int* rowp, const int* c8p)
{
    const int kv0 = t * 64;
    const uint32_t so = sb + (uint32_t)p * ASTAGE;
#pragma unroll
    for (int i = 0; i < 2; i++) {
        const uint32_t off = rowp[i] * STRAB + c8p[i] * 2;
        cp16(so + off,             khg  + (size_t)(kv0 + rowp[i]) * DK + c8p[i]);
        cp16(so + ATILE + off,     klg  + (size_t)(kv0 + rowp[i]) * DK + c8p[i]);
        cp16(so + 2 * ATILE + off, vthg + (size_t)rowp[i] * KCAP + kv0 + c8p[i]);
        cp16(so + 3 * ATILE + off, vtlg + (size_t)rowp[i] * KCAP + kv0 + c8p[i]);
    }
}

__global__ void __launch_bounds__(256, 1)
attn_mma(const float* __restrict__ Q, float* __restrict__ out)
{
    extern __shared__ char smem[];
    const uint32_t sb = smem_to_u32(smem);
    const int tid  = threadIdx.x;
    const int w    = tid >> 5;
    const int lane = tid & 31;
    const int g    = lane >> 2;
    const int tg   = lane & 3;
    const int h = blockIdx.y, b = blockIdx.z;
    const int bh = b * NHEADS + h;

    const int cq0 = g_cnt[bh * 2];
    const int ck0 = g_cnt[bh * 2 + 1];
    int xt = blockIdx.x;
    const int qt0 = (cq0 + 127) >> 7;
    int q0, ckg, kvb;
    if (xt < qt0) {
        q0 = xt * 128; ckg = ck0; kvb = 0;
    } else {
        xt -= qt0;
        const int cq1 = LSEQ - cq0;
        if (xt >= ((cq1 + 127) >> 7)) return;
        q0  = ((cq0 + 127) & ~127) + xt * 128;
        ckg = LSEQ - ck0;
        kvb = (ck0 + 63) & ~63;
    }
    const int nkt = (ckg + 63) >> 6;

    const __half* khg  = g_kh  + ((size_t)bh * KCAP + kvb) * DK;
    const __half* klg  = g_kl  + ((size_t)bh * KCAP + kvb) * DK;
    const __half* vthg = g_vth + (size_t)bh * DK * KCAP + kvb;
    const __half* vtlg = g_vtl + (size_t)bh * DK * KCAP + kvb;
    const int*    pq   = g_permq + bh * KCAP;

    int rowp[2], c8p[2];
#pragma unroll
    for (int i = 0; i < 2; i++) {
        const int idx = i * 256 + tid;
        rowp[i] = idx >> 3;
        c8p[i]  = (idx & 7) << 3;
    }

    const int src0 = pq[q0 + 16 * w + g];
    const int src1 = pq[q0 + 16 * w + g + 8];
    uint32_t qh[4][4], ql[4][4];
    {
        const float* qg0 = Q + ((size_t)bh * LSEQ + max(src0, 0)) * DK;
        const float* qg1 = Q + ((size_t)bh * LSEQ + max(src1, 0)) * DK;
#pragma unroll
        for (int s = 0; s < 4; s++) {
            const int k0 = 16 * s + 2 * tg;
            split2h(qg0[k0],     qg0[k0 + 1], qh[s][0], ql[s][0]);
            split2h(qg1[k0],     qg1[k0 + 1], qh[s][1], ql[s][1]);
            split2h(qg0[k0 + 8], qg0[k0 + 9], qh[s][2], ql[s][2]);
            split2h(qg1[k0 + 8], qg1[k0 + 9], qh[s][3], ql[s][3]);
        }
    }

    load_kv(sb, 0, 0, khg, klg, vthg, vtlg, rowp, c8p);
    CP_COMMIT;
    load_kv(sb, 1, 1, khg, klg, vthg, vtlg, rowp, c8p);
    CP_COMMIT;

    float o[8][4];
#pragma unroll
    for (int n = 0; n < 8; n++)
#pragma unroll
        for (int r = 0; r < 4; r++) o[n][r] = 0.f;
    float l0 = 0.f, l1 = 0.f;

    const uint32_t kRowOff = (uint32_t)(lane & 7) * STRAB + (uint32_t)(lane >> 3) * 16;
    const uint32_t vRowOff = (uint32_t)((lane & 7) + ((lane >> 4) << 3)) * STRAB
                           + (uint32_t)((lane >> 3) & 1) * 16;

    for (int t = 0; t < nkt; t++) {
        const int p = t & 1;
        if (t < nkt - 1) { CP_WAIT1; } else { CP_WAIT0; }
        __syncthreads();

        const uint32_t stb = sb + (uint32_t)p * ASTAGE;
        const uint32_t kHa = stb + kRowOff;
        const uint32_t kLa = kHa + ATILE;
        const uint32_t vHa = stb + 2 * ATILE + vRowOff;
        const uint32_t vLa = vHa + ATILE;

#pragma unroll
        for (int jj = 0; jj < 4; jj++) {
            float cA[2][4], cB[2][4];
#pragma unroll
            for (int u = 0; u < 2; u++)
#pragma unroll
                for (int r = 0; r < 4; r++) { cA[u][r] = 0.f; cB[u][r] = 0.f; }
#pragma unroll
            for (int u = 0; u < 2; u++) {
                const uint32_t kjh = kHa + (uint32_t)(2 * jj + u) * 8 * STRAB;
                const uint32_t kjl = kLa + (uint32_t)(2 * jj + u) * 8 * STRAB;
                uint32_t kf[8], lf[8];
                ldsm4(kf[0], kf[1], kf[2], kf[3], kjh);
                ldsm4(kf[4], kf[5], kf[6], kf[7], kjh + 64);
                ldsm4(lf[0], lf[1], lf[2], lf[3], kjl);
                ldsm4(lf[4], lf[5], lf[6], lf[7], kjl + 64);
#pragma unroll
                for (int s = 0; s < 4; s++) {
                    mma_f16(cA[u][0], cA[u][1], cA[u][2], cA[u][3],
                            qh[s][0], qh[s][1], qh[s][2], qh[s][3], kf[2 * s], kf[2 * s + 1]);
                    mma_f16(cB[u][0], cB[u][1], cB[u][2], cB[u][3],
                            ql[s][0], ql[s][1], ql[s][2], ql[s][3], kf[2 * s], kf[2 * s + 1]);
                    mma_f16(cB[u][0], cB[u][1], cB[u][2], cB[u][3],
                            qh[s][0], qh[s][1], qh[s][2], qh[s][3], lf[2 * s], lf[2 * s + 1]);
                }
            }
            uint32_t pA[4], pL[4];
#pragma unroll
            for (int u = 0; u < 2; u++) {
                const int idx0 = t * 64 + jj * 16 + u * 8 + 2 * tg;
                const bool v0 = idx0 < ckg;
                const bool v1 = idx0 + 1 < ckg;
                const float p0 = v0 ? __expf(fmaf(cA[u][0] + cB[u][0], 0.125f, -MSHIFT)) : 0.f;
                const float p1 = v1 ? __expf(fmaf(cA[u][1] + cB[u][1], 0.125f, -MSHIFT)) : 0.f;
                const float p2 = v0 ? __expf(fmaf(cA[u][2] + cB[u][2], 0.125f, -MSHIFT)) : 0.f;
                const float p3 = v1 ? __expf(fmaf(cA[u][3] + cB[u][3], 0.125f, -MSHIFT)) : 0.f;
                l0 += p0 + p1;
                l1 += p2 + p3;
                split2h(p0, p1, pA[0 + u * 2], pL[0 + u * 2]);
                split2h(p2, p3, pA[1 + u * 2], pL[1 + u * 2]);
            }
            uint32_t vf[16], wf[16];
            const uint32_t vj = vHa + (uint32_t)jj * 32;
            const uint32_t wj = vLa + (uint32_t)jj * 32;
#pragma unroll
            for (int pr = 0; pr < 4; pr++) {
                ldsm4(vf[4 * pr], vf[4 * pr + 1], vf[4 * pr + 2], vf[4 * pr + 3],
                      vj + (uint32_t)pr * 16 * STRAB);
                ldsm4(wf[4 * pr], wf[4 * pr + 1], wf[4 * pr + 2], wf[4 * pr + 3],
                      wj + (uint32_t)pr * 16 * STRAB);
            }
#pragma unroll
            for (int n = 0; n < 8; n++) {
                const int bi = 2 * n;
                mma_f16(o[n][0], o[n][1], o[n][2], o[n][3],
                        pA[0], pA[1], pA[2], pA[3], vf[bi], vf[bi + 1]);
            }
#pragma unroll
            for (int n = 0; n < 8; n++) {
                const int bi = 2 * n;
                mma_f16(o[n][0], o[n][1], o[n][2], o[n][3],
                        pL[0], pL[1], pL[2], pL[3], vf[bi], vf[bi + 1]);
            }
#pragma unroll
            for (int n = 0; n < 8; n++) {
                const int bi = 2 * n;
                mma_f16(o[n][0], o[n][1], o[n][2], o[n][3],
                        pA[0], pA[1], pA[2], pA[3], wf[bi], wf[bi + 1]);
            }
        }
        __syncthreads();
        if (t + 2 < nkt) {
            load_kv(sb, p, t + 2, khg, klg, vthg, vtlg, rowp, c8p);
            CP_COMMIT;
        }
    }

    l0 += __shfl_xor_sync(0xffffffffu, l0, 1);
    l0 += __shfl_xor_sync(0xffffffffu, l0, 2);
    l1 += __shfl_xor_sync(0xffffffffu, l1, 1);
    l1 += __shfl_xor_sync(0xffffffffu, l1, 2);
    const float il0 = 1.f / l0;
    const float il1 = 1.f / l1;

    if (src0 >= 0) {
        float* orow0 = out + (size_t)(b * LSEQ + src0) * DMODEL + h * DK + 2 * tg;
#pragma unroll
        for (int n = 0; n < 8; n++)
            *(float2*)(orow0 + 8 * n) = make_float2(o[n][0] * il0, o[n][1] * il0);
    }
    if (src1 >= 0) {
        float* orow1 = out + (size_t)(b * LSEQ + src1) * DMODEL + h * DK + 2 * tg;
#pragma unroll
        for (int n = 0; n < 8; n++)
            *(float2*)(orow1 + 8 * n) = make_float2(o[n][2] * il1, o[n][3] * il1);
    }
}

// ===========================================================================
// Launch
// ===========================================================================
extern "C" void kernel_launch(void* const* d_in, const int* in_sizes, int n_in,
                              void* d_out, int out_size)
{
    const float* query  = (const float*)d_in[0];
    const float* key    = (const float*)d_in[1];
    const float* value  = (const float*)d_in[2];
    const int*   hash_q = (const int*)d_in[3];
    const int*   hash_k = (const int*)d_in[4];
    const float* Wq     = (const float*)d_in[5];
    const float* bq     = (const float*)d_in[6];
    const float* Wk     = (const float*)d_in[7];
    const float* bk     = (const float*)d_in[8];
    const float* Wv     = (const float*)d_in[9];
    const float* bv     = (const float*)d_in[10];
    float* out = (float*)d_out;

    float* gq;
    cudaGetSymbolAddress((void**)&gq, g_q);

    cudaFuncSetAttribute(proj_mma, cudaFuncAttributeMaxDynamicSharedMemorySize, PROJ_SMEM);
    cudaFuncSetAttribute(attn_mma, cudaFuncAttributeMaxDynamicSharedMemorySize, ATT_SMEM);

    // fused pre-split of all 6 operands
    dim3 sg(MROWS * DMODEL / (4 * 256), 6);  // (4096, 6); W jobs early-exit above 1024
    split_all<<<sg, 256>>>(query, key, value, Wq, Wk, Wv);

    dim3 pg(MROWS / 128, DMODEL / 128, 3);   // (32, 8, 3) = 768 CTAs (R14-proven)
    proj_mma<<<pg, 256, PROJ_SMEM>>>(bq, bk, bv);

    build_perm<<<NBH, 64>>>(hash_q, hash_k);

    dim3 gg(144, 2, NBH);                    // merged K-gather + V-gather/transpose
    gather_kv<<<gg, 256>>>();

    dim3 ag(17, NHEADS, BATCH);
    attn_mma<<<ag, 256, ATT_SMEM>>>(gq, out);
}